// round 5
// baseline (speedup 1.0000x reference)
#include <cuda_runtime.h>
#include <cstddef>

#define BB   2
#define SS   2048
#define DD   1024
#define HH   16
#define DKK  64

__device__ float g_q[(size_t)BB * HH * SS * DKK];    // (B,H,S,DK)
__device__ float g_k[(size_t)BB * HH * SS * DKK];
__device__ float g_v[(size_t)BB * HH * SS * DKK];
__device__ float g_ctx[(size_t)BB * SS * DD];        // (B,S,D)

// ---------------------------------------------------------------------------
// NN SGEMM: C = A[M,K] @ W[K,N]. 128x128 tile, BK=16, 256 thr, 8x8/thread.
// headsplit!=0: write as (B,H,S,DK): row=b*S+s, col=h*DK+d.
// ---------------------------------------------------------------------------
__global__ void sgemm_nn128(const float* __restrict__ A, const float* __restrict__ W,
                            float* __restrict__ out, int M, int N, int K, int headsplit)
{
    __shared__ float As[16][128];   // [k][m]
    __shared__ float Bs[16][128];   // [k][n]

    const int tid = threadIdx.x;
    const int tx = tid & 15, ty = tid >> 4;
    const int rowBase = blockIdx.y * 128;
    const int colBase = blockIdx.x * 128;

    float acc[8][8];
#pragma unroll
    for (int i = 0; i < 8; i++)
#pragma unroll
        for (int j = 0; j < 8; j++) acc[i][j] = 0.f;

    for (int k0 = 0; k0 < K; k0 += 16) {
#pragma unroll
        for (int s = 0; s < 2; s++) {
            int idx = tid * 2 + s;
            int ar = idx >> 2, ak = (idx & 3) << 2;       // 128 rows x 4 float4
            float4 a = *(const float4*)&A[(size_t)(rowBase + ar) * K + k0 + ak];
            As[ak + 0][ar] = a.x; As[ak + 1][ar] = a.y;
            As[ak + 2][ar] = a.z; As[ak + 3][ar] = a.w;
            int br = idx >> 5, bc = (idx & 31) << 2;      // 16 k x 32 float4
            *(float4*)&Bs[br][bc] =
                *(const float4*)&W[(size_t)(k0 + br) * N + colBase + bc];
        }
        __syncthreads();
#pragma unroll
        for (int k = 0; k < 16; k++) {
            float am[8], bn[8];
            *(float4*)&am[0] = *(float4*)&As[k][ty * 8];
            *(float4*)&am[4] = *(float4*)&As[k][ty * 8 + 4];
            *(float4*)&bn[0] = *(float4*)&Bs[k][tx * 8];
            *(float4*)&bn[4] = *(float4*)&Bs[k][tx * 8 + 4];
#pragma unroll
            for (int mi = 0; mi < 8; mi++)
#pragma unroll
                for (int ni = 0; ni < 8; ni++)
                    acc[mi][ni] += am[mi] * bn[ni];
        }
        __syncthreads();
    }

#pragma unroll
    for (int mi = 0; mi < 8; mi++) {
        int row = rowBase + ty * 8 + mi;
#pragma unroll
        for (int ni = 0; ni < 8; ni++) {
            int col = colBase + tx * 8 + ni;
            float v = acc[mi][ni];
            if (headsplit) {
                int b = row >> 11;
                int s = row & (SS - 1);
                int h = col >> 6;
                int d = col & (DKK - 1);
                out[((((size_t)b * HH + h) * SS + s) * DKK) + d] = v;
            } else {
                out[(size_t)row * N + col] = v;
            }
        }
    }
}

// ---------------------------------------------------------------------------
// Scores: S_ij = (Q_i . K_j)/8, causal. 128x128 tile, NT, K=64, BK=16.
// Tiles strictly above the diagonal are skipped (never written).
// ---------------------------------------------------------------------------
__global__ void scores_nt128(const float* __restrict__ Q, const float* __restrict__ Km,
                             float* __restrict__ attn)
{
    const int jT = blockIdx.x, iT = blockIdx.y, bh = blockIdx.z;
    if (jT > iT) return;

    __shared__ float As[16][128];   // [k][i]
    __shared__ float Bs[16][128];   // [k][j]

    const float* Qb = Q + (size_t)bh * SS * DKK;
    const float* Kb = Km + (size_t)bh * SS * DKK;
    float* Ab = attn + (size_t)bh * SS * SS;

    const int tid = threadIdx.x;
    const int tx = tid & 15, ty = tid >> 4;

    float acc[8][8];
#pragma unroll
    for (int i = 0; i < 8; i++)
#pragma unroll
        for (int j = 0; j < 8; j++) acc[i][j] = 0.f;

    for (int k0 = 0; k0 < DKK; k0 += 16) {
#pragma unroll
        for (int s = 0; s < 2; s++) {
            int idx = tid * 2 + s;
            int r = idx >> 2, kk = (idx & 3) << 2;
            float4 a = *(const float4*)&Qb[(size_t)(iT * 128 + r) * DKK + k0 + kk];
            As[kk + 0][r] = a.x; As[kk + 1][r] = a.y;
            As[kk + 2][r] = a.z; As[kk + 3][r] = a.w;
            float4 b = *(const float4*)&Kb[(size_t)(jT * 128 + r) * DKK + k0 + kk];
            Bs[kk + 0][r] = b.x; Bs[kk + 1][r] = b.y;
            Bs[kk + 2][r] = b.z; Bs[kk + 3][r] = b.w;
        }
        __syncthreads();
#pragma unroll
        for (int k = 0; k < 16; k++) {
            float am[8], bn[8];
            *(float4*)&am[0] = *(float4*)&As[k][ty * 8];
            *(float4*)&am[4] = *(float4*)&As[k][ty * 8 + 4];
            *(float4*)&bn[0] = *(float4*)&Bs[k][tx * 8];
            *(float4*)&bn[4] = *(float4*)&Bs[k][tx * 8 + 4];
#pragma unroll
            for (int mi = 0; mi < 8; mi++)
#pragma unroll
                for (int ni = 0; ni < 8; ni++)
                    acc[mi][ni] += am[mi] * bn[ni];
        }
        __syncthreads();
    }

    const bool diag = (jT == iT);
#pragma unroll
    for (int mi = 0; mi < 8; mi++) {
        int i = iT * 128 + ty * 8 + mi;
#pragma unroll
        for (int ni = 0; ni < 8; ni++) {
            int j = jT * 128 + tx * 8 + ni;
            float v = acc[mi][ni] * 0.125f;
            if (diag && j > i) v = -1e9f;
            Ab[(size_t)i * SS + j] = v;
        }
    }
}

// ---------------------------------------------------------------------------
// Single-pass softmax: row cached in registers (8 vals/thread x 256 thr = 2048).
// Live region is j < n, n = 128-tile-rounded row limit. Tail zero-filled.
// ---------------------------------------------------------------------------
__global__ void softmax_rows(float* __restrict__ attn)
{
    const int row = blockIdx.x;
    const int i = row & (SS - 1);
    float* p = attn + (size_t)row * SS;
    const int n = ((i >> 7) + 1) << 7;       // 128-granular live width
    const int tid = threadIdx.x;

    __shared__ float red[256];

    float v[8];
    float m = -1e30f;
#pragma unroll
    for (int t = 0; t < 8; t++) {
        int j = t * 256 + tid;
        v[t] = (j < n) ? p[j] : -1e30f;
        m = fmaxf(m, v[t]);
    }
    red[tid] = m; __syncthreads();
    for (int s = 128; s > 0; s >>= 1) {
        if (tid < s) red[tid] = fmaxf(red[tid], red[tid + s]);
        __syncthreads();
    }
    const float mx = red[0]; __syncthreads();

    float sum = 0.f;
#pragma unroll
    for (int t = 0; t < 8; t++) {
        v[t] = __expf(v[t] - mx);
        sum += v[t];
    }
    red[tid] = sum; __syncthreads();
    for (int s = 128; s > 0; s >>= 1) {
        if (tid < s) red[tid] += red[tid + s];
        __syncthreads();
    }
    const float inv = 1.f / red[0];

#pragma unroll
    for (int t = 0; t < 8; t++) {
        int j = t * 256 + tid;
        if (j < n) p[j] = v[t] * inv;
    }
    for (int j = n + tid; j < SS; j += 256) p[j] = 0.f;
}

// ---------------------------------------------------------------------------
// PV: ctx_bh = attn_bh[S,S] @ V_bh[S,64]; k truncated causally. 128x64 tile,
// BK=16, 256 thr, 8x4/thread. Writes (B,S,D).
// ---------------------------------------------------------------------------
__global__ void attn_pv(const float* __restrict__ attn, const float* __restrict__ V,
                        float* __restrict__ ctx)
{
    const int iT = blockIdx.x, bh = blockIdx.z;
    const float* Ab = attn + (size_t)bh * SS * SS;
    const float* Vb = V + (size_t)bh * SS * DKK;

    __shared__ float As[16][128];   // [k][m]
    __shared__ float Bs[16][64];    // [k][n]

    const int tid = threadIdx.x;
    const int tx = tid & 15, ty = tid >> 4;

    float acc[8][4];
#pragma unroll
    for (int i = 0; i < 8; i++)
#pragma unroll
        for (int j = 0; j < 4; j++) acc[i][j] = 0.f;

    const int kEnd = (iT + 1) * 128;
    for (int k0 = 0; k0 < kEnd; k0 += 16) {
#pragma unroll
        for (int s = 0; s < 2; s++) {
            int idx = tid * 2 + s;
            int ar = idx >> 2, ak = (idx & 3) << 2;
            float4 a = *(const float4*)&Ab[(size_t)(iT * 128 + ar) * SS + k0 + ak];
            As[ak + 0][ar] = a.x; As[ak + 1][ar] = a.y;
            As[ak + 2][ar] = a.z; As[ak + 3][ar] = a.w;
        }
        {
            int br = tid >> 4, bc = (tid & 15) << 2;      // 16 k x 16 float4
            *(float4*)&Bs[br][bc] =
                *(const float4*)&Vb[(size_t)(k0 + br) * DKK + bc];
        }
        __syncthreads();
#pragma unroll
        for (int k = 0; k < 16; k++) {
            float am[8], bn[4];
            *(float4*)&am[0] = *(float4*)&As[k][ty * 8];
            *(float4*)&am[4] = *(float4*)&As[k][ty * 8 + 4];
            *(float4*)&bn[0] = *(float4*)&Bs[k][tx * 4];
#pragma unroll
            for (int mi = 0; mi < 8; mi++)
#pragma unroll
                for (int ni = 0; ni < 4; ni++)
                    acc[mi][ni] += am[mi] * bn[ni];
        }
        __syncthreads();
    }

    const int b = bh >> 4;
    const int h = bh & 15;
#pragma unroll
    for (int mi = 0; mi < 8; mi++) {
        int s = iT * 128 + ty * 8 + mi;
#pragma unroll
        for (int ni = 0; ni < 4; ni++) {
            int d = tx * 4 + ni;
            ctx[(((size_t)b * SS + s) * DD) + h * DKK + d] = acc[mi][ni];
        }
    }
}

// ---------------------------------------------------------------------------
extern "C" void kernel_launch(void* const* d_in, const int* in_sizes, int n_in,
                              void* d_out, int out_size)
{
    const float* query = (const float*)d_in[0];
    const float* key_  = (const float*)d_in[1];
    const float* value = (const float*)d_in[2];
    const float* wq = (const float*)d_in[4];
    const float* wk = (const float*)d_in[5];
    const float* wv = (const float*)d_in[6];
    const float* wo = (const float*)d_in[7];

    float* out  = (float*)d_out;                       // (B,S,D)
    float* attn = out + (size_t)BB * SS * DD;          // (B,H,S,S)

    float *q, *k, *v, *ctx;
    cudaGetSymbolAddress((void**)&q,   g_q);
    cudaGetSymbolAddress((void**)&k,   g_k);
    cudaGetSymbolAddress((void**)&v,   g_v);
    cudaGetSymbolAddress((void**)&ctx, g_ctx);

    const int M = BB * SS;          // 4096

    dim3 blk(256);
    dim3 gProj(DD / 128, M / 128);  // 8 x 32
    sgemm_nn128<<<gProj, blk>>>(query, wq, q, M, DD, DD, 1);
    sgemm_nn128<<<gProj, blk>>>(key_,  wk, k, M, DD, DD, 1);
    sgemm_nn128<<<gProj, blk>>>(value, wv, v, M, DD, DD, 1);

    dim3 gScore(SS / 128, SS / 128, BB * HH);   // 16 x 16 x 32
    scores_nt128<<<gScore, blk>>>(q, k, attn);

    softmax_rows<<<BB * HH * SS, blk>>>(attn);

    dim3 gPV(SS / 128, 1, BB * HH);
    attn_pv<<<gPV, blk>>>(attn, v, ctx);

    sgemm_nn128<<<gProj, blk>>>(ctx, wo, out, M, DD, DD, 0);
}